// round 3
// baseline (speedup 1.0000x reference)
#include <cuda_runtime.h>
#include <cstdint>
#include <cstddef>

#define N_NODES   50000
#define N_EDGESC  800000
#define TILE_E    128
#define NTILES    (N_EDGESC / TILE_E)   // 6250 exact

// ---------------- device scratch (no allocations allowed) ----------------
__device__ int   g_is64;
__device__ int   g_combo[N_NODES];
__device__ float g_WLt[384 * 128];      // W_lin transposed: WLt[c][o] = W_lin[o][c]
__device__ float g_T[1900 * 256];       // per-combo: [0:128) = node@W1^T + b_lin, [128:256) = node@W2^T

__device__ __forceinline__ float swishf(float v) {
    // v * sigmoid(v) = v / (1 + exp(-v)); __expf+__fdividef ~2ulp, fine for 1e-3 tol
    return __fdividef(v, 1.0f + __expf(-v));
}

// ---------------- K0: detect int32 vs int64 index layout ----------------
__global__ void k_detect(const int* __restrict__ p) {
    __shared__ int any;
    if (threadIdx.x == 0) any = 0;
    __syncthreads();
    int bad = 0;
    for (int k = threadIdx.x; k < 2048; k += blockDim.x)
        if (p[2 * k + 1] != 0) bad = 1;   // int64 little-endian high words are 0 (values < 50000)
    if (bad) atomicOr(&any, 1);
    __syncthreads();
    if (threadIdx.x == 0) g_is64 = any ? 0 : 1;
}

// ---------------- K1: transpose W_lin [128][384] -> WLt [384][128] ----------------
__global__ void k_transpose(const float* __restrict__ Wlin) {
    int idx = blockIdx.x * blockDim.x + threadIdx.x;
    if (idx < 128 * 384) {
        int o = idx / 384, c = idx % 384;
        g_WLt[c * 128 + o] = Wlin[idx];
    }
}

// ---------------- K2: node -> combo index ----------------
__global__ void k_combo(const void* __restrict__ xp) {
    int n = blockIdx.x * blockDim.x + threadIdx.x;
    if (n >= N_NODES) return;
    int x0, x1;
    if (g_is64) {
        const long long* q = (const long long*)xp;
        x0 = (int)q[2 * n]; x1 = (int)q[2 * n + 1];
    } else {
        const int* q = (const int*)xp;
        x0 = q[2 * n]; x1 = q[2 * n + 1];
    }
    g_combo[n] = x0 * 95 + x1;
}

// ---------------- K3: build combo table T[1900][256] ----------------
// T[cb][o]       = b_lin[o] + sum_k node_cb[k]   * W_lin[o][k]        (k<128)
// T[cb][128+o]   =            sum_k node_cb[k]   * W_lin[o][128+k]
// node_cb = concat(resi_emb_w[r], atom_emb_w[a]),  cb = r*95+a
__global__ __launch_bounds__(256) void k_buildT(const float* __restrict__ resi,
                                                const float* __restrict__ atom,
                                                const float* __restrict__ blin) {
    extern __shared__ float sm[];
    float* Ws   = sm;           // 32768 floats: WLt rows 0..255 -> Ws[c*128+o]
    float* bl   = sm + 32768;   // 128
    float* femb = bl + 128;     // 128
    int t = threadIdx.x;
    for (int idx = t; idx < 32768; idx += 256) Ws[idx] = g_WLt[idx];
    if (t < 128) bl[t] = blin[t];

    for (int cb = blockIdx.x; cb < 1900; cb += gridDim.x) {
        __syncthreads();
        if (t < 64)        femb[t] = resi[(cb / 95) * 64 + t];
        else if (t < 128)  femb[t] = atom[(cb % 95) * 64 + (t - 64)];
        __syncthreads();
        int part = t >> 7;           // 0 -> T1 block, 1 -> T2 block
        int o    = t & 127;
        float s  = part ? 0.0f : bl[o];
        const float* w = Ws + part * 128 * 128 + o;
#pragma unroll 8
        for (int k = 0; k < 128; k++) s += femb[k] * w[k * 128];
        g_T[cb * 256 + part * 128 + o] = s;
    }
}

// ---------------- K4: fused edge kernel ----------------
// out[e][o] = swish( T1[c[i[e]]][o] + T2[c[j[e]]][o] + sum_k swish(rbf[e]·W_rbf[k]+b_rbf[k]) * W_lin[o][256+k] )
__global__ __launch_bounds__(256, 1) void k_edge(const float* __restrict__ rbf,
                                                 const void* __restrict__ ip,
                                                 const void* __restrict__ jp,
                                                 const float* __restrict__ Wrbf,
                                                 const float* __restrict__ brbf,
                                                 float* __restrict__ out) {
    extern __shared__ float sm[];
    float* At  = sm;               // [128 k][128 e]  rbf_h transposed  (64 KB)
    float* Wt  = sm + 16384;       // [128 k][128 o]  W3 transposed     (64 KB)
    float* Wr  = sm + 32768;       // [128 k][8]  W_rbf row + bias      (4 KB)
    int*   sci = (int*)(sm + 33792);   // 128 combo idx of i
    int*   scj = sci + 128;            // 128 combo idx of j

    const int t  = threadIdx.x;
    const int is64 = g_is64;

    // one-time per-block loads (persistent kernel)
    for (int idx = t; idx < 16384; idx += 256) Wt[idx] = g_WLt[256 * 128 + idx];
    if (t < 128) {
#pragma unroll
        for (int r = 0; r < 6; r++) Wr[t * 8 + r] = Wrbf[t * 6 + r];
        Wr[t * 8 + 6] = brbf[t];
    }

    const int tr = t >> 4;     // 0..15 -> edge span
    const int tc = t & 15;     // 0..15 -> output span
    const int el = t & 127;    // phase-A edge lane
    const int kb = t >> 7;     // phase-A k parity

    for (int tile = blockIdx.x; tile < NTILES; tile += gridDim.x) {
        const int e0 = tile * TILE_E;
        __syncthreads();   // protect At/sci reuse across tiles (also covers Wt on iter 0)

        // ---- stage indices: sci/scj = combo of endpoint nodes ----
        if (t < 128) {
            long long e = (long long)e0 + t;
            int iv, jv;
            if (is64) {
                iv = (int)((const long long*)ip)[e];
                jv = (int)((const long long*)jp)[e];
            } else {
                iv = ((const int*)ip)[e];
                jv = ((const int*)jp)[e];
            }
            sci[t] = g_combo[iv];
            scj[t] = g_combo[jv];
        }

        // ---- phase A: rbf_h = swish(rbf @ W_rbf^T + b_rbf), stored transposed ----
        float rv[6];
        {
            const float* rp = rbf + (size_t)(e0 + el) * 6;
#pragma unroll
            for (int r = 0; r < 6; r++) rv[r] = rp[r];
        }
#pragma unroll 4
        for (int rep = 0; rep < 64; rep++) {
            int k = rep * 2 + kb;                  // warp-uniform -> Wr broadcast LDS
            const float* w = Wr + k * 8;
            float v = w[6];
#pragma unroll
            for (int r = 0; r < 6; r++) v += rv[r] * w[r];
            At[k * 128 + el] = swishf(v);
        }
        __syncthreads();

        // ---- phase B: C[128e][128o] = At^T @ Wt  (8x8 register tile / thread) ----
        float acc[8][8];
#pragma unroll
        for (int a = 0; a < 8; a++)
#pragma unroll
            for (int b = 0; b < 8; b++) acc[a][b] = 0.0f;

#pragma unroll 4
        for (int k = 0; k < 128; k++) {
            float4 a0 = *(const float4*)(At + k * 128 + tr * 4);
            float4 a1 = *(const float4*)(At + k * 128 + 64 + tr * 4);
            float4 w0 = *(const float4*)(Wt + k * 128 + tc * 4);
            float4 w1 = *(const float4*)(Wt + k * 128 + 64 + tc * 4);
            float av[8] = {a0.x, a0.y, a0.z, a0.w, a1.x, a1.y, a1.z, a1.w};
            float wv[8] = {w0.x, w0.y, w0.z, w0.w, w1.x, w1.y, w1.z, w1.w};
#pragma unroll
            for (int a = 0; a < 8; a++)
#pragma unroll
                for (int b = 0; b < 8; b++) acc[a][b] += av[a] * wv[b];
        }

        // ---- epilogue: add gathered node projections, swish, streaming store ----
#pragma unroll
        for (int ea = 0; ea < 2; ea++) {
#pragma unroll
            for (int eu = 0; eu < 4; eu++) {
                int le = ea * 64 + tr * 4 + eu;       // local edge
                int ci = sci[le], cj = scj[le];
                const float* T1 = g_T + (size_t)ci * 256;        // includes b_lin
                const float* T2 = g_T + (size_t)cj * 256 + 128;
                float* op = out + (size_t)(e0 + le) * 128;
#pragma unroll
                for (int ob = 0; ob < 2; ob++) {
                    int oo = ob * 64 + tc * 4;
                    float4 t1 = *(const float4*)(T1 + oo);
                    float4 t2 = *(const float4*)(T2 + oo);
                    int ar = ea * 4 + eu, ac = ob * 4;
                    float4 r;
                    r.x = swishf(acc[ar][ac + 0] + t1.x + t2.x);
                    r.y = swishf(acc[ar][ac + 1] + t1.y + t2.y);
                    r.z = swishf(acc[ar][ac + 2] + t1.z + t2.z);
                    r.w = swishf(acc[ar][ac + 3] + t1.w + t2.w);
                    __stcs((float4*)(op + oo), r);    // streaming store: keep g_T in L2
                }
            }
        }
    }
}

// ---------------- launch ----------------
extern "C" void kernel_launch(void* const* d_in, const int* in_sizes, int n_in,
                              void* d_out, int out_size) {
    const void*  x    = d_in[0];
    const float* rbf  = (const float*)d_in[1];
    const void*  ip   = d_in[2];
    const void*  jp   = d_in[3];
    const float* resi = (const float*)d_in[4];
    const float* atom = (const float*)d_in[5];
    const float* Wrbf = (const float*)d_in[6];
    const float* brbf = (const float*)d_in[7];
    const float* Wlin = (const float*)d_in[8];
    const float* blin = (const float*)d_in[9];
    float* out = (float*)d_out;

    const int SMEM_T    = (32768 + 256) * 4;                 // 132 KB
    const int SMEM_EDGE = (16384 + 16384 + 1024) * 4 + 1024; // 133 KB
    cudaFuncSetAttribute(k_buildT, cudaFuncAttributeMaxDynamicSharedMemorySize, SMEM_T);
    cudaFuncSetAttribute(k_edge,   cudaFuncAttributeMaxDynamicSharedMemorySize, SMEM_EDGE);

    k_detect<<<1, 256>>>((const int*)ip);
    k_transpose<<<(128 * 384 + 255) / 256, 256>>>(Wlin);
    k_combo<<<(N_NODES + 255) / 256, 256>>>(x);
    k_buildT<<<148, 256, SMEM_T>>>(resi, atom, blin);
    k_edge<<<148, 256, SMEM_EDGE>>>(rbf, ip, jp, Wrbf, brbf, out);
}

// round 5
// speedup vs baseline: 2.3331x; 2.3331x over previous
#include <cuda_runtime.h>
#include <cstdint>
#include <cstddef>

#define N_NODES   50000
#define N_EDGESC  800000
#define TILE_E    128
#define NTILES    (N_EDGESC / TILE_E)   // 6250
#define GRID_EDGE 148
#define AS_STRIDE 132                   // pad: 132 mod 32 = 4 -> conflict-free frag loads

// ---------------- device scratch ----------------
__device__ int   g_is64;
__device__ int   g_combo[N_NODES];
__device__ float g_WLt[256 * 128];                 // W_lin^T rows 0..255 (for buildT)
__device__ __align__(16) float g_T[1900 * 256];    // [0:128)=node@W1^T+b_lin, [128:256)=node@W2^T

__device__ __forceinline__ float swishf(float v) {
    float th;
    asm("tanh.approx.f32 %0, %1;" : "=f"(th) : "f"(v * 0.5f));
    return 0.5f * v * (1.0f + th);
}
__device__ __forceinline__ uint32_t to_tf32(float v) {
    uint32_t r;
    asm("cvt.rna.tf32.f32 %0, %1;" : "=r"(r) : "f"(v));
    return r;
}
__device__ __forceinline__ void mma_tf32(float* c, const uint32_t* a, const uint32_t* b) {
    asm volatile(
        "mma.sync.aligned.m16n8k8.row.col.f32.tf32.tf32.f32 "
        "{%0,%1,%2,%3}, {%4,%5,%6,%7}, {%8,%9}, {%0,%1,%2,%3};"
        : "+f"(c[0]), "+f"(c[1]), "+f"(c[2]), "+f"(c[3])
        : "r"(a[0]), "r"(a[1]), "r"(a[2]), "r"(a[3]), "r"(b[0]), "r"(b[1]));
}

// ---------------- prep kernels ----------------
__global__ void k_detect(const int* __restrict__ p) {
    __shared__ int any;
    if (threadIdx.x == 0) any = 0;
    __syncthreads();
    int bad = 0;
    for (int k = threadIdx.x; k < 2048; k += blockDim.x)
        if (p[2 * k + 1] != 0) bad = 1;
    if (bad) atomicOr(&any, 1);
    __syncthreads();
    if (threadIdx.x == 0) g_is64 = any ? 0 : 1;
}

__global__ void k_transpose(const float* __restrict__ Wlin) {
    int idx = blockIdx.x * blockDim.x + threadIdx.x;
    if (idx < 128 * 256) {
        int o = idx >> 8, c = idx & 255;
        g_WLt[c * 128 + o] = Wlin[o * 384 + c];
    }
}

__global__ void k_combo(const void* __restrict__ xp) {
    int n = blockIdx.x * blockDim.x + threadIdx.x;
    if (n >= N_NODES) return;
    int x0, x1;
    if (g_is64) {
        const long long* q = (const long long*)xp;
        x0 = (int)q[2 * n]; x1 = (int)q[2 * n + 1];
    } else {
        const int* q = (const int*)xp;
        x0 = q[2 * n]; x1 = q[2 * n + 1];
    }
    g_combo[n] = x0 * 95 + x1;
}

// buildT: 4 combos per block iteration; W streamed from L2-resident g_WLt
__global__ __launch_bounds__(256) void k_buildT(const float* __restrict__ resi,
                                                const float* __restrict__ atom,
                                                const float* __restrict__ blin) {
    __shared__ float femb[4][128];
    __shared__ float bl[128];
    int t = threadIdx.x;
    if (t < 128) bl[t] = blin[t];
    for (int cb0 = blockIdx.x * 4; cb0 < 1900; cb0 += gridDim.x * 4) {
        __syncthreads();
        for (int idx = t; idx < 512; idx += 256) {
            int c = idx >> 7, f = idx & 127;
            int cb = cb0 + c;
            float val = 0.f;
            if (cb < 1900)
                val = (f < 64) ? resi[(cb / 95) * 64 + f] : atom[(cb % 95) * 64 + (f - 64)];
            femb[c][f] = val;
        }
        __syncthreads();
        int part = t >> 7, o = t & 127;
        float s0 = part ? 0.f : bl[o], s1 = s0, s2 = s0, s3 = s0;
        const float* wp = g_WLt + part * 16384 + o;
#pragma unroll 4
        for (int k = 0; k < 128; k++) {
            float wv = __ldg(wp + k * 128);
            s0 = fmaf(femb[0][k], wv, s0);
            s1 = fmaf(femb[1][k], wv, s1);
            s2 = fmaf(femb[2][k], wv, s2);
            s3 = fmaf(femb[3][k], wv, s3);
        }
        float s[4] = {s0, s1, s2, s3};
#pragma unroll
        for (int c = 0; c < 4; c++)
            if (cb0 + c < 1900) g_T[(size_t)(cb0 + c) * 256 + part * 128 + o] = s[c];
    }
}

// ---------------- fused edge kernel (mma.sync tf32) ----------------
// SMEM (floats): As[128][132] | Bt[128][132] | Wr9[128*9] | sci[128] | scj[128]
#define AS_FL   0
#define BT_FL   (128 * AS_STRIDE)
#define WR_FL   (2 * 128 * AS_STRIDE)
#define SCI_FL  (WR_FL + 128 * 9)
#define SCJ_FL  (SCI_FL + 128)
#define SMEM_FL (SCJ_FL + 128)
#define SMEM_EDGE (SMEM_FL * 4)

__global__ __launch_bounds__(256, 1) void k_edge(const float* __restrict__ rbf,
                                                 const void* __restrict__ ip,
                                                 const void* __restrict__ jp,
                                                 const float* __restrict__ Wrbf,
                                                 const float* __restrict__ brbf,
                                                 const float* __restrict__ Wlin,
                                                 float* __restrict__ out) {
    extern __shared__ __align__(16) float sm[];
    float* As  = sm + AS_FL;
    float* Bt  = sm + BT_FL;
    float* Wr9 = sm + WR_FL;
    int*   sci = (int*)(sm + SCI_FL);
    int*   scj = (int*)(sm + SCJ_FL);

    const int t = threadIdx.x;
    const int w = t >> 5, l = t & 31;
    const int g = l >> 2, ctig = l & 3;
    const int is64 = g_is64;

    // prologue: Bt[o][k] = tf32(W_lin[o][256+k]); Wrbf+bias rows
    for (int idx = t; idx < 16384; idx += 256) {
        int o = idx >> 7, k = idx & 127;
        Bt[o * AS_STRIDE + k] = __uint_as_float(to_tf32(Wlin[o * 384 + 256 + k]));
    }
    if (t < 128) {
#pragma unroll
        for (int r = 0; r < 6; r++) Wr9[t * 9 + r] = Wrbf[t * 6 + r];
        Wr9[t * 9 + 6] = brbf[t];
    }
    __syncthreads();

    const int m0 = (w >> 2) * 64;   // warp edge base
    const int n0 = (w & 3) * 32;    // warp output base
    const int r0 = w * 8 + g;       // phase-A edge lane (0..63)

    for (int tile = blockIdx.x; tile < NTILES; tile += gridDim.x) {
        const int e0 = tile * TILE_E;

        // ---- phase A: indices + rbf_h = swish(rbf@Wrbf^T + b), tf32, into As ----
        if (t < 128) {
            int e = e0 + t;
            int iv, jv;
            if (is64) {
                iv = (int)((const long long*)ip)[e];
                jv = (int)((const long long*)jp)[e];
            } else {
                iv = ((const int*)ip)[e];
                jv = ((const int*)jp)[e];
            }
            sci[t] = g_combo[iv];
            scj[t] = g_combo[jv];
        }
        {
            float rv[2][6];
            const float* rp0 = rbf + (size_t)(e0 + r0) * 6;
            const float* rp1 = rbf + (size_t)(e0 + 64 + r0) * 6;
#pragma unroll
            for (int r = 0; r < 6; r++) { rv[0][r] = __ldg(rp0 + r); rv[1][r] = __ldg(rp1 + r); }
#pragma unroll
            for (int it = 0; it < 4; it++) {
                int k0 = it * 32 + ctig * 8;
                float wreg[8][7];
#pragma unroll
                for (int kk = 0; kk < 8; kk++)
#pragma unroll
                    for (int r = 0; r < 7; r++) wreg[kk][r] = Wr9[(k0 + kk) * 9 + r];
#pragma unroll
                for (int h = 0; h < 2; h++) {
                    int row = h * 64 + r0;
                    float v[8];
#pragma unroll
                    for (int kk = 0; kk < 8; kk++) {
                        float s = wreg[kk][6];
#pragma unroll
                        for (int r = 0; r < 6; r++) s = fmaf(rv[h][r], wreg[kk][r], s);
                        v[kk] = __uint_as_float(to_tf32(swishf(s)));
                    }
                    float* dst = As + row * AS_STRIDE + k0;
                    *(float4*)(dst)     = make_float4(v[0], v[1], v[2], v[3]);
                    *(float4*)(dst + 4) = make_float4(v[4], v[5], v[6], v[7]);
                }
            }
        }
        __syncthreads();

        // ---- phase B: 64x32 warp tile, m16n8k8 tf32 mma ----
        float acc[4][4][4];
#pragma unroll
        for (int f = 0; f < 4; f++)
#pragma unroll
            for (int h = 0; h < 4; h++)
#pragma unroll
                for (int c = 0; c < 4; c++) acc[f][h][c] = 0.f;

#pragma unroll 2
        for (int k0 = 0; k0 < 128; k0 += 8) {
            uint32_t a[4][4], b[4][2];
#pragma unroll
            for (int f = 0; f < 4; f++) {
                const uint32_t* p =
                    (const uint32_t*)As + (m0 + 16 * f + g) * AS_STRIDE + k0 + ctig;
                a[f][0] = p[0];
                a[f][1] = p[8 * AS_STRIDE];
                a[f][2] = p[4];
                a[f][3] = p[8 * AS_STRIDE + 4];
            }
#pragma unroll
            for (int h = 0; h < 4; h++) {
                const uint32_t* q =
                    (const uint32_t*)Bt + (n0 + 8 * h + g) * AS_STRIDE + k0 + ctig;
                b[h][0] = q[0];
                b[h][1] = q[4];
            }
#pragma unroll
            for (int f = 0; f < 4; f++)
#pragma unroll
                for (int h = 0; h < 4; h++) mma_tf32(acc[f][h], a[f], b[h]);
        }

        // ---- epilogue: gather T1/T2, add, swish, streaming store ----
#pragma unroll
        for (int f = 0; f < 4; f++) {
            const int ra = m0 + 16 * f + g;
            const int rb = ra + 8;
            const float2* T1a = (const float2*)(g_T + (size_t)sci[ra] * 256);
            const float2* T2a = (const float2*)(g_T + (size_t)scj[ra] * 256 + 128);
            const float2* T1b = (const float2*)(g_T + (size_t)sci[rb] * 256);
            const float2* T2b = (const float2*)(g_T + (size_t)scj[rb] * 256 + 128);
            float2* oa = (float2*)(out + (size_t)(e0 + ra) * 128);
            float2* ob = (float2*)(out + (size_t)(e0 + rb) * 128);
#pragma unroll
            for (int h = 0; h < 4; h++) {
                const int c2 = ((n0 + 8 * h) >> 1) + ctig;
                float2 t1 = __ldg(T1a + c2), t2 = __ldg(T2a + c2);
                float2 r;
                r.x = swishf(acc[f][h][0] + t1.x + t2.x);
                r.y = swishf(acc[f][h][1] + t1.y + t2.y);
                __stcs(oa + c2, r);
                t1 = __ldg(T1b + c2); t2 = __ldg(T2b + c2);
                r.x = swishf(acc[f][h][2] + t1.x + t2.x);
                r.y = swishf(acc[f][h][3] + t1.y + t2.y);
                __stcs(ob + c2, r);
            }
        }
        __syncthreads();   // protect As/sci rewrite next tile
    }
}

// ---------------- launch ----------------
extern "C" void kernel_launch(void* const* d_in, const int* in_sizes, int n_in,
                              void* d_out, int out_size) {
    const void*  x    = d_in[0];
    const float* rbf  = (const float*)d_in[1];
    const void*  ip   = d_in[2];
    const void*  jp   = d_in[3];
    const float* resi = (const float*)d_in[4];
    const float* atom = (const float*)d_in[5];
    const float* Wrbf = (const float*)d_in[6];
    const float* brbf = (const float*)d_in[7];
    const float* Wlin = (const float*)d_in[8];
    const float* blin = (const float*)d_in[9];
    float* out = (float*)d_out;

    cudaFuncSetAttribute(k_edge, cudaFuncAttributeMaxDynamicSharedMemorySize, SMEM_EDGE);

    k_detect<<<1, 256>>>((const int*)ip);
    k_transpose<<<(128 * 256 + 255) / 256, 256>>>(Wlin);
    k_combo<<<(N_NODES + 255) / 256, 256>>>(x);
    k_buildT<<<148, 256>>>(resi, atom, blin);
    k_edge<<<GRID_EDGE, 256, SMEM_EDGE>>>(rbf, ip, jp, Wrbf, brbf, Wlin, out);
}

// round 9
// speedup vs baseline: 3.1529x; 1.3513x over previous
#include <cuda_runtime.h>
#include <cuda_fp16.h>
#include <cstdint>
#include <cstddef>
#include <cstring>

#define N_NODES   50000
#define N_EDGESC  800000
#define TILE_E    128
#define NTILES    (N_EDGESC / TILE_E)   // 6250
#define GRID_EDGE 296
#define AS_H      136                   // half stride (272 B): pad for ldmatrix conflict-freedom

// ---------------- device scratch ----------------
__device__ int    g_is64;
__device__ int    g_combo[N_NODES];
__device__ float  g_WLt[256 * 128];                    // W_lin^T rows 0..255 (fp32, for buildT)
__device__ __align__(4) __half g_Th[1900 * 256];       // combo table fp16: [0:128)=n@W1^T+b, [128:256)=n@W2^T

__device__ __forceinline__ float swishf(float v) {
    float th;
    asm("tanh.approx.f32 %0, %1;" : "=f"(th) : "f"(v * 0.5f));
    return 0.5f * v * (1.0f + th);
}
__device__ __forceinline__ uint32_t smem_u32(const void* p) {
    uint32_t a;
    asm("{ .reg .u64 t; cvta.to.shared.u64 t, %1; cvt.u32.u64 %0, t; }" : "=r"(a) : "l"(p));
    return a;
}
__device__ __forceinline__ uint32_t h2_bits(__half2 h) {
    uint32_t u;
    memcpy(&u, &h, 4);
    return u;
}
#define LDSM_X4(r0, r1, r2, r3, addr) \
    asm volatile("ldmatrix.sync.aligned.m8n8.x4.shared.b16 {%0,%1,%2,%3}, [%4];" \
                 : "=r"(r0), "=r"(r1), "=r"(r2), "=r"(r3) : "r"(addr))
__device__ __forceinline__ void mma_f16(float* c, const uint32_t* a, uint32_t b0, uint32_t b1) {
    asm volatile(
        "mma.sync.aligned.m16n8k16.row.col.f32.f16.f16.f32 "
        "{%0,%1,%2,%3}, {%4,%5,%6,%7}, {%8,%9}, {%0,%1,%2,%3};"
        : "+f"(c[0]), "+f"(c[1]), "+f"(c[2]), "+f"(c[3])
        : "r"(a[0]), "r"(a[1]), "r"(a[2]), "r"(a[3]), "r"(b0), "r"(b1));
}

// ---------------- prep kernels ----------------
__global__ void k_detect(const int* __restrict__ p) {
    __shared__ int any;
    if (threadIdx.x == 0) any = 0;
    __syncthreads();
    int bad = 0;
    for (int k = threadIdx.x; k < 2048; k += blockDim.x)
        if (p[2 * k + 1] != 0) bad = 1;
    if (bad) atomicOr(&any, 1);
    __syncthreads();
    if (threadIdx.x == 0) g_is64 = any ? 0 : 1;
}

__global__ void k_transpose(const float* __restrict__ Wlin) {
    int idx = blockIdx.x * blockDim.x + threadIdx.x;
    if (idx < 128 * 256) {
        int o = idx >> 8, c = idx & 255;
        g_WLt[c * 128 + o] = Wlin[o * 384 + c];
    }
}

__global__ void k_combo(const void* __restrict__ xp) {
    int n = blockIdx.x * blockDim.x + threadIdx.x;
    if (n >= N_NODES) return;
    int x0, x1;
    if (g_is64) {
        const long long* q = (const long long*)xp;
        x0 = (int)q[2 * n]; x1 = (int)q[2 * n + 1];
    } else {
        const int* q = (const int*)xp;
        x0 = q[2 * n]; x1 = q[2 * n + 1];
    }
    g_combo[n] = x0 * 95 + x1;
}

// buildT: one 4-combo group per block (grid 475); unroll 16 -> MLP hides L2 latency
__global__ __launch_bounds__(256) void k_buildT(const float* __restrict__ resi,
                                                const float* __restrict__ atom,
                                                const float* __restrict__ blin) {
    __shared__ float femb[4][128];
    __shared__ float bl[128];
    int t = threadIdx.x;
    if (t < 128) bl[t] = blin[t];
    int cb0 = blockIdx.x * 4;
    for (int idx = t; idx < 512; idx += 256) {
        int c = idx >> 7, f = idx & 127;
        int cb = cb0 + c;
        float val = 0.f;
        if (cb < 1900)
            val = (f < 64) ? resi[(cb / 95) * 64 + f] : atom[(cb % 95) * 64 + (f - 64)];
        femb[c][f] = val;
    }
    __syncthreads();
    int part = t >> 7, o = t & 127;
    float s0 = part ? 0.f : bl[o], s1 = s0, s2 = s0, s3 = s0;
    const float* wp = g_WLt + part * 16384 + o;
#pragma unroll 16
    for (int k = 0; k < 128; k++) {
        float wv = __ldg(wp + k * 128);
        s0 = fmaf(femb[0][k], wv, s0);
        s1 = fmaf(femb[1][k], wv, s1);
        s2 = fmaf(femb[2][k], wv, s2);
        s3 = fmaf(femb[3][k], wv, s3);
    }
    float s[4] = {s0, s1, s2, s3};
#pragma unroll
    for (int c = 0; c < 4; c++)
        if (cb0 + c < 1900)
            g_Th[(size_t)(cb0 + c) * 256 + part * 128 + o] = __float2half_rn(s[c]);
}

// ---------------- fused edge kernel (fp16 mma + ldmatrix) ----------------
#define SMEM_EDGE ((2 * 128 * AS_H) * 2 + 128 * 9 * 4 + 256 * 4)

__global__ __launch_bounds__(256, 2) void k_edge(const float* __restrict__ rbf,
                                                 const void* __restrict__ ip,
                                                 const void* __restrict__ jp,
                                                 const float* __restrict__ Wrbf,
                                                 const float* __restrict__ brbf,
                                                 const float* __restrict__ Wlin,
                                                 float* __restrict__ out) {
    extern __shared__ __align__(16) char smemc[];
    __half* As  = (__half*)smemc;
    __half* Bt  = As + 128 * AS_H;
    float*  Wr9 = (float*)(Bt + 128 * AS_H);
    int*    sci = (int*)(Wr9 + 128 * 9);
    int*    scj = sci + 128;

    const int t = threadIdx.x;
    const int w = t >> 5, l = t & 31;
    const int g = l >> 2, ctig = l & 3;
    const int is64 = g_is64;

    // prologue: Bt[o][k] = fp16(W_lin[o][256+k]); Wr9 = W_rbf rows + bias
    for (int idx = t; idx < 8192; idx += 256) {
        int o = idx >> 6, k2 = idx & 63;
        float2 wv = __ldg((const float2*)(Wlin + o * 384 + 256) + k2);
        *(__half2*)(Bt + o * AS_H + 2 * k2) = __floats2half2_rn(wv.x, wv.y);
    }
    if (t < 128) {
#pragma unroll
        for (int r = 0; r < 6; r++) Wr9[t * 9 + r] = Wrbf[t * 6 + r];
        Wr9[t * 9 + 6] = brbf[t];
    }
    __syncthreads();

    const int m0 = (w >> 2) * 64;   // warp edge base (phase B)
    const int n0 = (w & 3) * 32;    // warp output base
    const int kg = l;               // phase A: lane owns k = 4*kg .. 4*kg+3
    const int eb = w * 16;          // phase A: warp owns 16 edges

    // ldmatrix lane addresses (constant across tiles)
    const uint32_t sbase = smem_u32(smemc);
    const int lrow = l & 15;
    const uint32_t lk = (uint32_t)((l >> 4) * 16);   // +8 halves in bytes
    uint32_t aAddr[4], bAddr[2];
#pragma unroll
    for (int f = 0; f < 4; f++)
        aAddr[f] = sbase + (uint32_t)((m0 + 16 * f + lrow) * AS_H * 2) + lk;
#pragma unroll
    for (int h2 = 0; h2 < 2; h2++)
        bAddr[h2] = sbase + (uint32_t)(128 * AS_H * 2) +
                    (uint32_t)((n0 + 16 * h2 + lrow) * AS_H * 2) + lk;

    for (int tile = blockIdx.x; tile < NTILES; tile += gridDim.x) {
        const int e0 = tile * TILE_E;

        // ---- stage combo indices ----
        if (t < 128) {
            int e = e0 + t;
            int iv, jv;
            if (is64) {
                iv = (int)((const long long*)ip)[e];
                jv = (int)((const long long*)jp)[e];
            } else {
                iv = ((const int*)ip)[e];
                jv = ((const int*)jp)[e];
            }
            sci[t] = g_combo[iv];
            scj[t] = g_combo[jv];
        }

        // ---- phase A: As[e][k] = fp16(swish(rbf[e] . Wrbf[k] + b[k])) ----
        {
            float wreg[4][7];
#pragma unroll
            for (int kk = 0; kk < 4; kk++)
#pragma unroll
                for (int r = 0; r < 7; r++) wreg[kk][r] = Wr9[(4 * kg + kk) * 9 + r];
#pragma unroll 4
            for (int ei = 0; ei < 16; ei++) {
                const int e = eb + ei;
                const float2* rp = (const float2*)(rbf + (size_t)(e0 + e) * 6);
                float2 r01 = __ldg(rp), r23 = __ldg(rp + 1), r45 = __ldg(rp + 2);
                float v[4];
#pragma unroll
                for (int kk = 0; kk < 4; kk++) {
                    float s = wreg[kk][6];
                    s = fmaf(r01.x, wreg[kk][0], s);
                    s = fmaf(r01.y, wreg[kk][1], s);
                    s = fmaf(r23.x, wreg[kk][2], s);
                    s = fmaf(r23.y, wreg[kk][3], s);
                    s = fmaf(r45.x, wreg[kk][4], s);
                    s = fmaf(r45.y, wreg[kk][5], s);
                    v[kk] = swishf(s);
                }
                uint2 pk;
                pk.x = h2_bits(__floats2half2_rn(v[0], v[1]));
                pk.y = h2_bits(__floats2half2_rn(v[2], v[3]));
                *(uint2*)(As + e * AS_H + 4 * kg) = pk;
            }
        }
        __syncthreads();

        // ---- phase B: 64x32 warp tile, m16n8k16 fp16 mma via ldmatrix ----
        float acc[4][4][4];
#pragma unroll
        for (int f = 0; f < 4; f++)
#pragma unroll
            for (int h = 0; h < 4; h++)
#pragma unroll
                for (int c = 0; c < 4; c++) acc[f][h][c] = 0.f;

#pragma unroll
        for (int ks = 0; ks < 8; ks++) {
            const uint32_t ko = (uint32_t)(ks * 32);   // 16 halves = 32 B
            uint32_t b0, b1, b2, b3, b4, b5, b6, b7;
            LDSM_X4(b0, b1, b2, b3, bAddr[0] + ko);
            LDSM_X4(b4, b5, b6, b7, bAddr[1] + ko);
#pragma unroll
            for (int f = 0; f < 4; f++) {
                uint32_t a[4];
                LDSM_X4(a[0], a[1], a[2], a[3], aAddr[f] + ko);
                mma_f16(acc[f][0], a, b0, b2);
                mma_f16(acc[f][1], a, b1, b3);
                mma_f16(acc[f][2], a, b4, b6);
                mma_f16(acc[f][3], a, b5, b7);
            }
        }

        // ---- epilogue: fp16 table gather + add + swish + streaming store ----
#pragma unroll
        for (int f = 0; f < 4; f++) {
            const int ra = m0 + 16 * f + g;
            const int rb = ra + 8;
            const __half* T1a = g_Th + (size_t)sci[ra] * 256;
            const __half* T2a = g_Th + (size_t)scj[ra] * 256 + 128;
            const __half* T1b = g_Th + (size_t)sci[rb] * 256;
            const __half* T2b = g_Th + (size_t)scj[rb] * 256 + 128;
            float* oa = out + (size_t)(e0 + ra) * 128;
            float* ob = out + (size_t)(e0 + rb) * 128;
#pragma unroll
            for (int h = 0; h < 4; h++) {
                const int col = n0 + 8 * h + 2 * ctig;
                float2 t1 = __half22float2(__ldg((const __half2*)(T1a + col)));
                float2 t2 = __half22float2(__ldg((const __half2*)(T2a + col)));
                float2 r;
                r.x = swishf(acc[f][h][0] + t1.x + t2.x);
                r.y = swishf(acc[f][h][1] + t1.y + t2.y);
                __stcs((float2*)(oa + col), r);
                t1 = __half22float2(__ldg((const __half2*)(T1b + col)));
                t2 = __half22float2(__ldg((const __half2*)(T2b + col)));
                r.x = swishf(acc[f][h][2] + t1.x + t2.x);
                r.y = swishf(acc[f][h][3] + t1.y + t2.y);
                __stcs((float2*)(ob + col), r);
            }
        }
        __syncthreads();   // As/sci rewrite protection for next tile
    }
}

// ---------------- launch ----------------
extern "C" void kernel_launch(void* const* d_in, const int* in_sizes, int n_in,
                              void* d_out, int out_size) {
    const void*  x    = d_in[0];
    const float* rbf  = (const float*)d_in[1];
    const void*  ip   = d_in[2];
    const void*  jp   = d_in[3];
    const float* resi = (const float*)d_in[4];
    const float* atom = (const float*)d_in[5];
    const float* Wrbf = (const float*)d_in[6];
    const float* brbf = (const float*)d_in[7];
    const float* Wlin = (const float*)d_in[8];
    const float* blin = (const float*)d_in[9];
    float* out = (float*)d_out;

    cudaFuncSetAttribute(k_edge, cudaFuncAttributeMaxDynamicSharedMemorySize, SMEM_EDGE);

    k_detect<<<1, 256>>>((const int*)ip);
    k_transpose<<<(128 * 256 + 255) / 256, 256>>>(Wlin);
    k_combo<<<(N_NODES + 255) / 256, 256>>>(x);
    k_buildT<<<475, 256>>>(resi, atom, blin);
    k_edge<<<GRID_EDGE, 256, SMEM_EDGE>>>(rbf, ip, jp, Wrbf, brbf, Wlin, out);
}